// round 2
// baseline (speedup 1.0000x reference)
#include <cuda_runtime.h>
#include <cuda_bf16.h>
#include <math.h>

// Problem dims
#define NTOK 16384      // B*S
#define DIM  4096       // D
#define HID  2048       // H
#define NEXP 64         // experts
#define TOPK 3

// Output layout (float32, concatenated flattened reference outputs)
#define OFF_W 0
#define OFF_I (NTOK * TOPK)                   // 49152
#define OFF_M (2 * NTOK * TOPK)               // 98304
#define OFF_K (2 * NTOK * TOPK + NTOK * NEXP) // 1146880

// Scratch (device globals: allocation-free per harness rules)
__device__ float g_h[(size_t)NTOK * HID];        // 134 MB: relu(x@W1+b1)
__device__ float g_logits[(size_t)NTOK * NEXP];  // 4 MB:   x@W
__device__ int   g_kdyn[NTOK];

// ---------------------------------------------------------------------------
// GEMM1: g_h = relu(x @ W1 + b1).  M=16384, N=2048, K=4096.
// 128x128x8 tile, 256 threads, 8x8 per thread. (fp32; feeds only dynamic_k,
// which is boundary-robust — weights output passed at 4.6e-6.)
// ---------------------------------------------------------------------------
__global__ __launch_bounds__(256) void sgemm_h(
    const float* __restrict__ A,   // x [M,K]
    const float* __restrict__ B,   // W1 [K,N]
    const float* __restrict__ bias // b1 [N]
) {
    const int N = HID, K = DIM;
    __shared__ float As[8][128];
    __shared__ float Bs[8][128];

    const int tid = threadIdx.x;
    const int m0 = blockIdx.y * 128;
    const int n0 = blockIdx.x * 128;

    const int aRow = tid >> 1;            // 0..127
    const int aCol = (tid & 1) * 4;       // 0 or 4
    const int bRow = tid >> 5;            // 0..7
    const int bCol = (tid & 31) * 4;      // 0..124

    const float* Ap = A + (size_t)(m0 + aRow) * K + aCol;
    const float* Bp = B + (size_t)bRow * N + n0 + bCol;

    const int ty = tid >> 4;              // 0..15
    const int tx = tid & 15;              // 0..15

    float acc[8][8];
    #pragma unroll
    for (int i = 0; i < 8; i++)
        #pragma unroll
        for (int j = 0; j < 8; j++) acc[i][j] = 0.f;

    for (int k0 = 0; k0 < K; k0 += 8) {
        float4 av = *(const float4*)(Ap + k0);
        float4 bv = *(const float4*)(Bp + (size_t)k0 * N);
        __syncthreads();
        As[aCol + 0][aRow] = av.x;
        As[aCol + 1][aRow] = av.y;
        As[aCol + 2][aRow] = av.z;
        As[aCol + 3][aRow] = av.w;
        *(float4*)&Bs[bRow][bCol] = bv;
        __syncthreads();

        #pragma unroll
        for (int kk = 0; kk < 8; kk++) {
            float a[8], b[8];
            *(float4*)&a[0] = *(const float4*)&As[kk][ty * 8 + 0];
            *(float4*)&a[4] = *(const float4*)&As[kk][ty * 8 + 4];
            *(float4*)&b[0] = *(const float4*)&Bs[kk][tx * 8 + 0];
            *(float4*)&b[4] = *(const float4*)&Bs[kk][tx * 8 + 4];
            #pragma unroll
            for (int i = 0; i < 8; i++)
                #pragma unroll
                for (int j = 0; j < 8; j++)
                    acc[i][j] = fmaf(a[i], b[j], acc[i][j]);
        }
    }

    #pragma unroll
    for (int i = 0; i < 8; i++) {
        const int row = m0 + ty * 8 + i;
        float* Cp = g_h + (size_t)row * N + n0 + tx * 8;
        float4 v0, v1;
        v0.x = fmaxf(acc[i][0] + bias[n0 + tx * 8 + 0], 0.f);
        v0.y = fmaxf(acc[i][1] + bias[n0 + tx * 8 + 1], 0.f);
        v0.z = fmaxf(acc[i][2] + bias[n0 + tx * 8 + 2], 0.f);
        v0.w = fmaxf(acc[i][3] + bias[n0 + tx * 8 + 3], 0.f);
        v1.x = fmaxf(acc[i][4] + bias[n0 + tx * 8 + 4], 0.f);
        v1.y = fmaxf(acc[i][5] + bias[n0 + tx * 8 + 5], 0.f);
        v1.z = fmaxf(acc[i][6] + bias[n0 + tx * 8 + 6], 0.f);
        v1.w = fmaxf(acc[i][7] + bias[n0 + tx * 8 + 7], 0.f);
        *(float4*)(Cp + 0) = v0;
        *(float4*)(Cp + 4) = v1;
    }
}

// ---------------------------------------------------------------------------
// GEMM2 (high accuracy): g_logits = x @ W.  M=16384, N=64, K=4096.
// Block: 64 tokens x 64 experts, 256 threads, each thread 4x4 outputs.
// fp32 partials over 8-term sub-chunks, flushed into fp64 accumulators
// => logit abs error ~5e-7 (vs ~1.7e-5 before) so top-k ranking is stable.
// ---------------------------------------------------------------------------
__global__ __launch_bounds__(256) void gemm_logits(
    const float* __restrict__ A,   // x [M,K]
    const float* __restrict__ B    // W [K,64]
) {
    const int K = DIM;
    __shared__ float As_t[32][64];   // [k][token]
    __shared__ float Bs[32][64];     // [k][expert]

    const int tid = threadIdx.x;
    const int m0 = blockIdx.x * 64;

    const int tg4 = (tid >> 4) * 4;  // token group base (0..60)
    const int eg4 = (tid & 15) * 4;  // expert group base (0..60)

    double acc[4][4];
    #pragma unroll
    for (int i = 0; i < 4; i++)
        #pragma unroll
        for (int j = 0; j < 4; j++) acc[i][j] = 0.0;

    // A-tile load mapping: 64 rows x 8 float4 per row = 512 float4, 2 per thread
    const int ar = tid >> 3;         // 0..31 (row within 32-row half)
    const int ac = (tid & 7) * 4;    // 0..28 (k offset, x4)

    for (int k0 = 0; k0 < K; k0 += 32) {
        __syncthreads();
        // Load A [64 tokens x 32 k], store transposed As_t[k][token]
        #pragma unroll
        for (int it = 0; it < 2; it++) {
            const int r = it * 32 + ar;   // token row 0..63
            float4 av = *(const float4*)(A + (size_t)(m0 + r) * K + k0 + ac);
            As_t[ac + 0][r] = av.x;
            As_t[ac + 1][r] = av.y;
            As_t[ac + 2][r] = av.z;
            As_t[ac + 3][r] = av.w;
        }
        // Load B [32 k x 64 experts]: 512 float4, 2 per thread
        #pragma unroll
        for (int it = 0; it < 2; it++) {
            const int f = tid * 2 + it;        // 0..511
            const int kk = f >> 4;             // 0..31
            const int e4 = (f & 15) * 4;       // 0..60
            *(float4*)&Bs[kk][e4] = *(const float4*)(B + (size_t)(k0 + kk) * NEXP + e4);
        }
        __syncthreads();

        float part[4][4];
        #pragma unroll
        for (int i = 0; i < 4; i++)
            #pragma unroll
            for (int j = 0; j < 4; j++) part[i][j] = 0.f;

        #pragma unroll
        for (int kk = 0; kk < 32; kk++) {
            float4 a = *(const float4*)&As_t[kk][tg4];
            float4 b = *(const float4*)&Bs[kk][eg4];
            float av[4] = {a.x, a.y, a.z, a.w};
            float bv[4] = {b.x, b.y, b.z, b.w};
            #pragma unroll
            for (int i = 0; i < 4; i++)
                #pragma unroll
                for (int j = 0; j < 4; j++)
                    part[i][j] = fmaf(av[i], bv[j], part[i][j]);
            if ((kk & 7) == 7) {
                #pragma unroll
                for (int i = 0; i < 4; i++)
                    #pragma unroll
                    for (int j = 0; j < 4; j++) {
                        acc[i][j] += (double)part[i][j];
                        part[i][j] = 0.f;
                    }
            }
        }
    }

    #pragma unroll
    for (int i = 0; i < 4; i++) {
        const int row = m0 + tg4 + i;
        #pragma unroll
        for (int j = 0; j < 4; j++)
            g_logits[(size_t)row * NEXP + eg4 + j] = (float)acc[i][j];
    }
}

// ---------------------------------------------------------------------------
// z = h @ W2 + b2 -> sigmoid -> dynamic_k per token. One block per token.
// Deterministic tree reduction (graph replays bitwise stable).
// ---------------------------------------------------------------------------
__global__ __launch_bounds__(256) void predictor_k(
    const float* __restrict__ W2, const float* __restrict__ b2
) {
    __shared__ float red[256];
    const int n = blockIdx.x;
    const int tid = threadIdx.x;
    const float4* hp = (const float4*)(g_h + (size_t)n * HID);
    const float4* wp = (const float4*)W2;
    float acc = 0.f;
    #pragma unroll
    for (int j = tid; j < HID / 4; j += 256) {
        float4 h4 = hp[j];
        float4 w4 = wp[j];
        acc = fmaf(h4.x, w4.x, acc);
        acc = fmaf(h4.y, w4.y, acc);
        acc = fmaf(h4.z, w4.z, acc);
        acc = fmaf(h4.w, w4.w, acc);
    }
    red[tid] = acc;
    __syncthreads();
    for (int s = 128; s > 0; s >>= 1) {
        if (tid < s) red[tid] += red[tid + s];
        __syncthreads();
    }
    if (tid == 0) {
        float z = red[0] + b2[0];
        float score = 1.0f / (1.0f + expf(-z));
        float kf = rintf(score * 3.0f) + 1.0f;   // round-half-even == jnp.round
        kf = fminf(fmaxf(kf, 1.0f), 3.0f);
        g_kdyn[n] = (int)kf;
    }
}

// ---------------------------------------------------------------------------
// Finalize: softmax over 64, top-3 on ROUNDED probs (ties -> lower index,
// exactly matching jax.lax.top_k), dynamic-k mask + renorm, routing mask.
// One warp per token.
// ---------------------------------------------------------------------------
__global__ __launch_bounds__(256) void finalize(float* __restrict__ out) {
    const int warp = threadIdx.x >> 5;
    const int lane = threadIdx.x & 31;
    const int n = blockIdx.x * 8 + warp;

    const float* lp = g_logits + (size_t)n * NEXP;
    float l0 = lp[lane];
    float l1 = lp[lane + 32];

    // max
    float m = fmaxf(l0, l1);
    #pragma unroll
    for (int o = 16; o > 0; o >>= 1) m = fmaxf(m, __shfl_xor_sync(0xFFFFFFFFu, m, o));
    // exp + sum
    float e0 = expf(l0 - m);
    float e1 = expf(l1 - m);
    float s = e0 + e1;
    #pragma unroll
    for (int o = 16; o > 0; o >>= 1) s += __shfl_xor_sync(0xFFFFFFFFu, s, o);

    // rounded probabilities — same values jax.lax.top_k compares
    float p0 = e0 / s;
    float p1 = e1 / s;

    float c0 = p0, c1 = p1;
    float tv[TOPK];
    int   ti[TOPK];
    #pragma unroll
    for (int r = 0; r < TOPK; r++) {
        float v;
        int idx;
        if (c1 > c0) { v = c1; idx = lane + 32; }   // strict: ties -> lower idx
        else         { v = c0; idx = lane; }
        #pragma unroll
        for (int o = 16; o > 0; o >>= 1) {
            float ov = __shfl_xor_sync(0xFFFFFFFFu, v, o);
            int   oi = __shfl_xor_sync(0xFFFFFFFFu, idx, o);
            if (ov > v || (ov == v && oi < idx)) { v = ov; idx = oi; }
        }
        tv[r] = v;
        ti[r] = idx;
        if (idx == lane)      c0 = -1.0f;
        if (idx == lane + 32) c1 = -1.0f;
    }

    const int k = g_kdyn[n];

    float msum = 0.f;
    #pragma unroll
    for (int r = 0; r < TOPK; r++)
        if (r < k) msum += tv[r];
    const float denom = msum + 1e-8f;

    if (lane < TOPK) {
        float w = (lane < k ? tv[lane] : 0.f) / denom;
        out[OFF_W + (size_t)n * TOPK + lane] = w;
        out[OFF_I + (size_t)n * TOPK + lane] = (float)ti[lane];
    }

    float m0v = 0.f, m1v = 0.f;
    #pragma unroll
    for (int r = 0; r < TOPK; r++) {
        if (r < k) {
            if (ti[r] == lane)      m0v = 1.0f;
            if (ti[r] == lane + 32) m1v = 1.0f;
        }
    }
    out[OFF_M + (size_t)n * NEXP + lane]      = m0v;
    out[OFF_M + (size_t)n * NEXP + lane + 32] = m1v;

    if (lane == 0) out[OFF_K + n] = (float)k;
}

// ---------------------------------------------------------------------------
extern "C" void kernel_launch(void* const* d_in, const int* in_sizes, int n_in,
                              void* d_out, int out_size) {
    const float* x  = (const float*)d_in[0];  // [B,S,D]
    const float* W  = (const float*)d_in[1];  // [D,E]
    const float* W1 = (const float*)d_in[2];  // [D,H]
    const float* b1 = (const float*)d_in[3];  // [H]
    const float* W2 = (const float*)d_in[4];  // [H,1]
    const float* b2 = (const float*)d_in[5];  // [1]
    float* out = (float*)d_out;

    sgemm_h<<<dim3(HID / 128, NTOK / 128), 256>>>(x, W1, b1);
    gemm_logits<<<NTOK / 64, 256>>>(x, W);
    predictor_k<<<NTOK, 256>>>(W2, b2);
    finalize<<<NTOK / 8, 256>>>(out);
}

// round 5
// speedup vs baseline: 1.0814x; 1.0814x over previous
#include <cuda_runtime.h>
#include <cuda_bf16.h>
#include <math.h>
#include <stdint.h>

// Problem dims
#define NTOK 16384      // B*S
#define DIM  4096       // D (K of both GEMMs)
#define HID  2048       // H (N of GEMM1)
#define NEXP 64
#define TOPK 3

// Output layout (float32, concatenated flattened reference outputs)
#define OFF_W 0
#define OFF_I (NTOK * TOPK)
#define OFF_M (2 * NTOK * TOPK)
#define OFF_K (2 * NTOK * TOPK + NTOK * NEXP)

// Scratch (device globals)
__device__ float g_h[(size_t)NTOK * HID];        // 134 MB
__device__ float g_logits[(size_t)NTOK * NEXP];  // 4 MB
__device__ int   g_kdyn[NTOK];

// ---------------------------------------------------------------------------
// Packed fp32x2 helpers (Blackwell base-target PTX: fma.rn.f32x2)
// ---------------------------------------------------------------------------
typedef unsigned long long ull;

__device__ __forceinline__ ull pack_dup(float a) {
    ull r;
    asm("mov.b64 %0, {%1, %1};" : "=l"(r) : "f"(a));
    return r;
}
__device__ __forceinline__ void fma2(ull& d, ull a, ull b) {
    asm("fma.rn.f32x2 %0, %1, %2, %3;" : "=l"(d) : "l"(a), "l"(b), "l"(d));
}
__device__ __forceinline__ float2 unpack2(ull v) {
    float2 f;
    asm("mov.b64 {%0, %1}, %2;" : "=f"(f.x), "=f"(f.y) : "l"(v));
    return f;
}

// ---------------------------------------------------------------------------
// GEMM1: g_h = relu(x @ W1 + b1).  M=16384, N=2048, K=4096.
// CTA tile 128x256, BK=8, 256 threads, 8 rows x 16 cols per thread,
// inner product via fma.rn.f32x2 (2 MACs/lane/instr => 2x FFMA roofline).
// ---------------------------------------------------------------------------
#define BM 128
#define BN 256
#define BK 8

__global__ __launch_bounds__(256, 1) void sgemm_h(
    const float* __restrict__ A,    // x [M,K]
    const float* __restrict__ B,    // W1 [K,N]
    const float* __restrict__ bias  // b1 [N]
) {
    const int N = HID, K = DIM;
    __shared__ float As[BK][BM];    // 4 KB
    __shared__ float Bs[BK][BN];    // 8 KB

    const int tid = threadIdx.x;
    const int m0 = blockIdx.y * BM;
    const int n0 = blockIdx.x * BN;

    // A loads: 128 rows x 8 k = 256 float4, 1 per thread
    const int aRow = tid >> 1;
    const int aCol = (tid & 1) * 4;
    // B loads: 8 k-rows x 256 cols = 512 float4, 2 consecutive per thread
    const int bRow = (tid * 2) >> 6;          // 0..7
    const int bCol = ((tid * 2) & 63) * 4;    // 0..252 step 8

    const float* Ap = A + (size_t)(m0 + aRow) * K + aCol;
    const float* Bp = B + (size_t)bRow * N + n0 + bCol;

    // compute mapping: 16x16 thread grid; 8 rows x 16 cols per thread.
    // thread's 16 cols = { 64*j + 4*tx + (0..3) : j=0..3 }
    const int ty = tid >> 4;   // 0..15 (row group of 8)
    const int tx = tid & 15;   // 0..15

    ull acc[8][8];             // [row][col-pair]; pairs (2j,2j+1) <-> float4 j
    #pragma unroll
    for (int i = 0; i < 8; i++)
        #pragma unroll
        for (int j = 0; j < 8; j++) acc[i][j] = 0ull;

    float4 av = *(const float4*)Ap;
    float4 bv0 = *(const float4*)Bp;
    float4 bv1 = *(const float4*)(Bp + 4);

    for (int k0 = 0; k0 < K; k0 += BK) {
        __syncthreads();
        As[aCol + 0][aRow] = av.x;
        As[aCol + 1][aRow] = av.y;
        As[aCol + 2][aRow] = av.z;
        As[aCol + 3][aRow] = av.w;
        *(float4*)&Bs[bRow][bCol]     = bv0;
        *(float4*)&Bs[bRow][bCol + 4] = bv1;
        __syncthreads();

        if (k0 + BK < K) {   // prefetch next chunk, overlapped with compute
            av  = *(const float4*)(Ap + k0 + BK);
            bv0 = *(const float4*)(Bp + (size_t)(k0 + BK) * N);
            bv1 = *(const float4*)(Bp + (size_t)(k0 + BK) * N + 4);
        }

        #pragma unroll
        for (int kk = 0; kk < BK; kk++) {
            ull a2[8];
            #pragma unroll
            for (int i = 0; i < 8; i++)
                a2[i] = pack_dup(As[kk][ty * 8 + i]);
            #pragma unroll
            for (int j = 0; j < 4; j++) {
                const ull* bp = (const ull*)&Bs[kk][j * 64 + tx * 4];
                ull b0 = bp[0];
                ull b1 = bp[1];
                #pragma unroll
                for (int i = 0; i < 8; i++) {
                    fma2(acc[i][2 * j],     a2[i], b0);
                    fma2(acc[i][2 * j + 1], a2[i], b1);
                }
            }
        }
    }

    // epilogue: bias + relu, fp32 store
    #pragma unroll
    for (int i = 0; i < 8; i++) {
        const int row = m0 + ty * 8 + i;
        float* dst = g_h + (size_t)row * N + n0;
        #pragma unroll
        for (int j = 0; j < 4; j++) {
            const int c = j * 64 + tx * 4;
            float2 p0 = unpack2(acc[i][2 * j]);
            float2 p1 = unpack2(acc[i][2 * j + 1]);
            float4 v;
            v.x = fmaxf(p0.x + bias[n0 + c + 0], 0.f);
            v.y = fmaxf(p0.y + bias[n0 + c + 1], 0.f);
            v.z = fmaxf(p1.x + bias[n0 + c + 2], 0.f);
            v.w = fmaxf(p1.y + bias[n0 + c + 3], 0.f);
            *(float4*)(dst + c) = v;
        }
    }
}

// ---------------------------------------------------------------------------
// GEMM2 (high accuracy): g_logits = x @ W.  fp32 partials over 8-term chunks
// flushed into fp64 accumulators (proven: rel_err 1e-6, ranking-stable).
// ---------------------------------------------------------------------------
__global__ __launch_bounds__(256) void gemm_logits(
    const float* __restrict__ A, const float* __restrict__ B
) {
    const int K = DIM;
    __shared__ float As_t[32][64];
    __shared__ float Bs[32][64];

    const int tid = threadIdx.x;
    const int m0 = blockIdx.x * 64;
    const int tg4 = (tid >> 4) * 4;
    const int eg4 = (tid & 15) * 4;

    double acc[4][4];
    #pragma unroll
    for (int i = 0; i < 4; i++)
        #pragma unroll
        for (int j = 0; j < 4; j++) acc[i][j] = 0.0;

    const int ar = tid >> 3;
    const int ac = (tid & 7) * 4;

    for (int k0 = 0; k0 < K; k0 += 32) {
        __syncthreads();
        #pragma unroll
        for (int it = 0; it < 2; it++) {
            const int r = it * 32 + ar;
            float4 av = *(const float4*)(A + (size_t)(m0 + r) * K + k0 + ac);
            As_t[ac + 0][r] = av.x;
            As_t[ac + 1][r] = av.y;
            As_t[ac + 2][r] = av.z;
            As_t[ac + 3][r] = av.w;
        }
        #pragma unroll
        for (int it = 0; it < 2; it++) {
            const int f = tid * 2 + it;
            const int kk = f >> 4;
            const int e4 = (f & 15) * 4;
            *(float4*)&Bs[kk][e4] = *(const float4*)(B + (size_t)(k0 + kk) * NEXP + e4);
        }
        __syncthreads();

        float part[4][4];
        #pragma unroll
        for (int i = 0; i < 4; i++)
            #pragma unroll
            for (int j = 0; j < 4; j++) part[i][j] = 0.f;

        #pragma unroll
        for (int kk = 0; kk < 32; kk++) {
            float4 a = *(const float4*)&As_t[kk][tg4];
            float4 b = *(const float4*)&Bs[kk][eg4];
            float av[4] = {a.x, a.y, a.z, a.w};
            float bv[4] = {b.x, b.y, b.z, b.w};
            #pragma unroll
            for (int i = 0; i < 4; i++)
                #pragma unroll
                for (int j = 0; j < 4; j++)
                    part[i][j] = fmaf(av[i], bv[j], part[i][j]);
            if ((kk & 7) == 7) {
                #pragma unroll
                for (int i = 0; i < 4; i++)
                    #pragma unroll
                    for (int j = 0; j < 4; j++) {
                        acc[i][j] += (double)part[i][j];
                        part[i][j] = 0.f;
                    }
            }
        }
    }

    #pragma unroll
    for (int i = 0; i < 4; i++) {
        const int row = m0 + tg4 + i;
        #pragma unroll
        for (int j = 0; j < 4; j++)
            g_logits[(size_t)row * NEXP + eg4 + j] = (float)acc[i][j];
    }
}

// ---------------------------------------------------------------------------
// predictor: z = h@W2 + b2 -> sigmoid -> dynamic_k (deterministic reduction)
// ---------------------------------------------------------------------------
__global__ __launch_bounds__(256) void predictor_k(
    const float* __restrict__ W2, const float* __restrict__ b2
) {
    __shared__ float red[256];
    const int n = blockIdx.x;
    const int tid = threadIdx.x;
    const float4* hp = (const float4*)(g_h + (size_t)n * HID);
    const float4* wp = (const float4*)W2;
    float acc = 0.f;
    #pragma unroll
    for (int j = tid; j < HID / 4; j += 256) {
        float4 h4 = hp[j];
        float4 w4 = wp[j];
        acc = fmaf(h4.x, w4.x, acc);
        acc = fmaf(h4.y, w4.y, acc);
        acc = fmaf(h4.z, w4.z, acc);
        acc = fmaf(h4.w, w4.w, acc);
    }
    red[tid] = acc;
    __syncthreads();
    for (int s = 128; s > 0; s >>= 1) {
        if (tid < s) red[tid] += red[tid + s];
        __syncthreads();
    }
    if (tid == 0) {
        float z = red[0] + b2[0];
        float score = 1.0f / (1.0f + expf(-z));
        float kf = rintf(score * 3.0f) + 1.0f;   // round-half-even == jnp.round
        kf = fminf(fmaxf(kf, 1.0f), 3.0f);
        g_kdyn[n] = (int)kf;
    }
}

// ---------------------------------------------------------------------------
// finalize: softmax/top-3 (rounded probs, lower-index ties)/mask/renorm
// ---------------------------------------------------------------------------
__global__ __launch_bounds__(256) void finalize(float* __restrict__ out) {
    const int warp = threadIdx.x >> 5;
    const int lane = threadIdx.x & 31;
    const int n = blockIdx.x * 8 + warp;

    const float* lp = g_logits + (size_t)n * NEXP;
    float l0 = lp[lane];
    float l1 = lp[lane + 32];

    float m = fmaxf(l0, l1);
    #pragma unroll
    for (int o = 16; o > 0; o >>= 1) m = fmaxf(m, __shfl_xor_sync(0xFFFFFFFFu, m, o));
    float e0 = expf(l0 - m);
    float e1 = expf(l1 - m);
    float s = e0 + e1;
    #pragma unroll
    for (int o = 16; o > 0; o >>= 1) s += __shfl_xor_sync(0xFFFFFFFFu, s, o);

    float p0 = e0 / s;
    float p1 = e1 / s;

    float c0 = p0, c1 = p1;
    float tv[TOPK];
    int   ti[TOPK];
    #pragma unroll
    for (int r = 0; r < TOPK; r++) {
        float v;
        int idx;
        if (c1 > c0) { v = c1; idx = lane + 32; }
        else         { v = c0; idx = lane; }
        #pragma unroll
        for (int o = 16; o > 0; o >>= 1) {
            float ov = __shfl_xor_sync(0xFFFFFFFFu, v, o);
            int   oi = __shfl_xor_sync(0xFFFFFFFFu, idx, o);
            if (ov > v || (ov == v && oi < idx)) { v = ov; idx = oi; }
        }
        tv[r] = v;
        ti[r] = idx;
        if (idx == lane)      c0 = -1.0f;
        if (idx == lane + 32) c1 = -1.0f;
    }

    const int k = g_kdyn[n];

    float msum = 0.f;
    #pragma unroll
    for (int r = 0; r < TOPK; r++)
        if (r < k) msum += tv[r];
    const float denom = msum + 1e-8f;

    if (lane < TOPK) {
        float w = (lane < k ? tv[lane] : 0.f) / denom;
        out[OFF_W + (size_t)n * TOPK + lane] = w;
        out[OFF_I + (size_t)n * TOPK + lane] = (float)ti[lane];
    }

    float m0v = 0.f, m1v = 0.f;
    #pragma unroll
    for (int r = 0; r < TOPK; r++) {
        if (r < k) {
            if (ti[r] == lane)      m0v = 1.0f;
            if (ti[r] == lane + 32) m1v = 1.0f;
        }
    }
    out[OFF_M + (size_t)n * NEXP + lane]      = m0v;
    out[OFF_M + (size_t)n * NEXP + lane + 32] = m1v;

    if (lane == 0) out[OFF_K + n] = (float)k;
}

// ---------------------------------------------------------------------------
extern "C" void kernel_launch(void* const* d_in, const int* in_sizes, int n_in,
                              void* d_out, int out_size) {
    const float* x  = (const float*)d_in[0];
    const float* W  = (const float*)d_in[1];
    const float* W1 = (const float*)d_in[2];
    const float* b1 = (const float*)d_in[3];
    const float* W2 = (const float*)d_in[4];
    const float* b2 = (const float*)d_in[5];
    float* out = (float*)d_out;

    sgemm_h<<<dim3(HID / BN, NTOK / BM), 256>>>(x, W1, b1);
    gemm_logits<<<NTOK / 64, 256>>>(x, W);
    predictor_k<<<NTOK, 256>>>(W2, b2);
    finalize<<<NTOK / 8, 256>>>(out);
}

// round 6
// speedup vs baseline: 1.2256x; 1.1334x over previous
#include <cuda_runtime.h>
#include <cuda_bf16.h>
#include <math.h>
#include <stdint.h>

// Problem dims
#define NTOK 16384      // B*S
#define DIM  4096       // D (K of both GEMMs)
#define HID  2048       // H (N of GEMM1)
#define NEXP 64
#define TOPK 3

// Output layout (float32, concatenated flattened reference outputs)
#define OFF_W 0
#define OFF_I (NTOK * TOPK)
#define OFF_M (2 * NTOK * TOPK)
#define OFF_K (2 * NTOK * TOPK + NTOK * NEXP)

// Scratch (device globals)
#define XPLANE ((size_t)NTOK * DIM)
#define WPLANE ((size_t)HID * DIM)
#define FLAG_CAP 2048
__device__ __align__(16) __nv_bfloat16 g_xs[2 * XPLANE];   // 268 MB: x 2-way splits
__device__ __align__(16) __nv_bfloat16 g_w1t[2 * WPLANE];  // 33 MB: W1^T 2-way splits [N][K]
__device__ float g_h[(size_t)NTOK * HID];                  // 134 MB
__device__ float g_logits[(size_t)NTOK * NEXP];            // 4 MB
__device__ int   g_kdyn[NTOK];
__device__ int   g_nflag;
__device__ int   g_flaglist[FLAG_CAP];

// ---------------------------------------------------------------------------
// PTX helpers (baseline sm_80+ ISA: ldmatrix / mma.sync / cp.async)
// ---------------------------------------------------------------------------
__device__ __forceinline__ uint32_t smem_u32(const void* p) {
    uint32_t a;
    asm("{ .reg .u64 t; cvta.to.shared.u64 t, %1; cvt.u32.u64 %0, t; }" : "=r"(a) : "l"(p));
    return a;
}
__device__ __forceinline__ void cp_async16(uint32_t dst, const void* src) {
    asm volatile("cp.async.cg.shared.global [%0], [%1], 16;" :: "r"(dst), "l"(src));
}
__device__ __forceinline__ void cp_commit() {
    asm volatile("cp.async.commit_group;");
}
template <int N>
__device__ __forceinline__ void cp_wait() {
    asm volatile("cp.async.wait_group %0;" :: "n"(N));
}
__device__ __forceinline__ void ldmatrix_x4(uint32_t& r0, uint32_t& r1, uint32_t& r2, uint32_t& r3,
                                            uint32_t addr) {
    asm volatile("ldmatrix.sync.aligned.m8n8.x4.shared.b16 {%0,%1,%2,%3}, [%4];"
                 : "=r"(r0), "=r"(r1), "=r"(r2), "=r"(r3) : "r"(addr));
}
__device__ __forceinline__ void mma_bf16(float* c, const uint32_t* a, const uint32_t* b) {
    asm volatile(
        "mma.sync.aligned.m16n8k16.row.col.f32.bf16.bf16.f32 "
        "{%0,%1,%2,%3}, {%4,%5,%6,%7}, {%8,%9}, {%0,%1,%2,%3};"
        : "+f"(c[0]), "+f"(c[1]), "+f"(c[2]), "+f"(c[3])
        : "r"(a[0]), "r"(a[1]), "r"(a[2]), "r"(a[3]), "r"(b[0]), "r"(b[1]));
}

// ---------------------------------------------------------------------------
// 2-way bf16 splits
// ---------------------------------------------------------------------------
__device__ __forceinline__ void split2(float v, __nv_bfloat16& a, __nv_bfloat16& b) {
    a = __float2bfloat16_rn(v);
    b = __float2bfloat16_rn(v - __bfloat162float(a));
}

__global__ __launch_bounds__(256) void split_x(const float* __restrict__ x) {
    size_t i = ((size_t)blockIdx.x * 256 + threadIdx.x) * 4;
    float4 v = *(const float4*)(x + i);
    __nv_bfloat16 a[4], b[4];
    split2(v.x, a[0], b[0]);
    split2(v.y, a[1], b[1]);
    split2(v.z, a[2], b[2]);
    split2(v.w, a[3], b[3]);
    ushort4 pa, pb;
    pa.x = __bfloat16_as_ushort(a[0]); pa.y = __bfloat16_as_ushort(a[1]);
    pa.z = __bfloat16_as_ushort(a[2]); pa.w = __bfloat16_as_ushort(a[3]);
    pb.x = __bfloat16_as_ushort(b[0]); pb.y = __bfloat16_as_ushort(b[1]);
    pb.z = __bfloat16_as_ushort(b[2]); pb.w = __bfloat16_as_ushort(b[3]);
    *(ushort4*)(g_xs + i)          = pa;
    *(ushort4*)(g_xs + XPLANE + i) = pb;
}

// W1 [K][N] fp32 -> W1^T [N][K] bf16 x2 (tiled transpose)
__global__ __launch_bounds__(256) void split_w1t(const float* __restrict__ W1) {
    __shared__ float t[32][33];
    const int k0 = blockIdx.x * 32;
    const int n0 = blockIdx.y * 32;
    const int tx = threadIdx.x;  // 0..31
    const int ty = threadIdx.y;  // 0..7
    #pragma unroll
    for (int j = 0; j < 4; j++)
        t[ty + 8 * j][tx] = W1[(size_t)(k0 + ty + 8 * j) * HID + n0 + tx];
    __syncthreads();
    #pragma unroll
    for (int j = 0; j < 4; j++) {
        const int n = n0 + ty + 8 * j;
        const int kk = k0 + tx;
        __nv_bfloat16 a, b;
        split2(t[tx][ty + 8 * j], a, b);
        g_w1t[(size_t)n * DIM + kk]          = a;
        g_w1t[WPLANE + (size_t)n * DIM + kk] = b;
    }
}

// ---------------------------------------------------------------------------
// GEMM1 via mma.sync bf16, 2-way split (3 passes into one fp32 accumulator):
//   h = relu(x1*w1 + x1*w2 + x2*w1 + b1)
// CTA 128x128, BK=32, 8 warps (2M x 4N), warp tile 64x32.
// SMEM row pitch 40 bf16 (80B) -> ldmatrix conflict-free.
// ---------------------------------------------------------------------------
#define G1_BM 128
#define G1_BN 128
#define G1_BK 32
#define PITCH 40                          // bf16 elements per smem row
#define TILE_B (128 * PITCH * 2)          // 10240 bytes per tile
#define STAGE_B (4 * TILE_B)              // A1,A2,B1,B2 = 40960
#define G1_SMEM (2 * STAGE_B)             // 81920
#define G1_NIT (DIM / G1_BK)              // 128

__global__ __launch_bounds__(256, 1) void gemm1_hmma(const float* __restrict__ bias) {
    extern __shared__ char smem[];
    const uint32_t sbase = smem_u32(smem);

    const int tid  = threadIdx.x;
    const int warp = tid >> 5;
    const int lane = tid & 31;
    const int m0 = blockIdx.y * G1_BM;
    const int n0 = blockIdx.x * G1_BN;

    const int wm = (warp >> 2) * 64;   // warp M offset (0 or 64)
    const int wn = (warp & 3) * 32;    // warp N offset

    // global load mapping: per split, thread covers row=tid>>1, chunks c0,c0+1
    const int gr = tid >> 1;
    const int gc = (tid & 1) * 2;

    float acc[4][4][4];   // [mb][nb][frag]
    #pragma unroll
    for (int i = 0; i < 4; i++)
        #pragma unroll
        for (int j = 0; j < 4; j++)
            #pragma unroll
            for (int q = 0; q < 4; q++) acc[i][j][q] = 0.f;

    // stage load: k0 = chunk base (element index)
    auto load_stage = [&](int stage, int k0) {
        const uint32_t sb = sbase + stage * STAGE_B;
        #pragma unroll
        for (int p = 0; p < 2; p++) {
            const __nv_bfloat16* asrc = g_xs + (size_t)p * XPLANE + (size_t)(m0 + gr) * DIM + k0;
            const uint32_t adst = sb + p * TILE_B + gr * (PITCH * 2);
            cp_async16(adst + (gc + 0) * 16, asrc + (gc + 0) * 8);
            cp_async16(adst + (gc + 1) * 16, asrc + (gc + 1) * 8);
            const __nv_bfloat16* bsrc = g_w1t + (size_t)p * WPLANE + (size_t)(n0 + gr) * DIM + k0;
            const uint32_t bdst = sb + (2 + p) * TILE_B + gr * (PITCH * 2);
            cp_async16(bdst + (gc + 0) * 16, bsrc + (gc + 0) * 8);
            cp_async16(bdst + (gc + 1) * 16, bsrc + (gc + 1) * 8);
        }
        cp_commit();
    };

    load_stage(0, 0);

    for (int it = 0; it < G1_NIT; it++) {
        if (it + 1 < G1_NIT) {
            load_stage((it + 1) & 1, (it + 1) * G1_BK);
            cp_wait<1>();
        } else {
            cp_wait<0>();
        }
        __syncthreads();

        const uint32_t sb = sbase + (it & 1) * STAGE_B;
        const uint32_t A1 = sb;
        const uint32_t A2 = sb + TILE_B;
        const uint32_t B1 = sb + 2 * TILE_B;
        const uint32_t B2 = sb + 3 * TILE_B;

        const int g = lane >> 3, r = lane & 7;

        #pragma unroll
        for (int s = 0; s < 2; s++) {          // two k16 steps
            uint32_t a1f[4][4], a2f[4][4];
            #pragma unroll
            for (int mb = 0; mb < 4; mb++) {
                const uint32_t off =
                    (uint32_t)(wm + mb * 16 + (g & 1) * 8 + r) * (PITCH * 2) + s * 32 + (g >> 1) * 16;
                ldmatrix_x4(a1f[mb][0], a1f[mb][1], a1f[mb][2], a1f[mb][3], A1 + off);
                ldmatrix_x4(a2f[mb][0], a2f[mb][1], a2f[mb][2], a2f[mb][3], A2 + off);
            }
            uint32_t b1f[4][2], b2f[4][2];
            #pragma unroll
            for (int nbp = 0; nbp < 2; nbp++) {
                const uint32_t off =
                    (uint32_t)(wn + nbp * 16 + (g >> 1) * 8 + r) * (PITCH * 2) + s * 32 + (g & 1) * 16;
                uint32_t q0, q1, q2, q3;
                ldmatrix_x4(q0, q1, q2, q3, B1 + off);
                b1f[nbp * 2][0] = q0; b1f[nbp * 2][1] = q1;
                b1f[nbp * 2 + 1][0] = q2; b1f[nbp * 2 + 1][1] = q3;
                ldmatrix_x4(q0, q1, q2, q3, B2 + off);
                b2f[nbp * 2][0] = q0; b2f[nbp * 2][1] = q1;
                b2f[nbp * 2 + 1][0] = q2; b2f[nbp * 2 + 1][1] = q3;
            }
            // pass 0: A1*B1
            #pragma unroll
            for (int mb = 0; mb < 4; mb++)
                #pragma unroll
                for (int nb = 0; nb < 4; nb++)
                    mma_bf16(acc[mb][nb], a1f[mb], b1f[nb]);
            // pass 1: A1*B2
            #pragma unroll
            for (int mb = 0; mb < 4; mb++)
                #pragma unroll
                for (int nb = 0; nb < 4; nb++)
                    mma_bf16(acc[mb][nb], a1f[mb], b2f[nb]);
            // pass 2: A2*B1
            #pragma unroll
            for (int mb = 0; mb < 4; mb++)
                #pragma unroll
                for (int nb = 0; nb < 4; nb++)
                    mma_bf16(acc[mb][nb], a2f[mb], b1f[nb]);
        }
        __syncthreads();
    }

    // epilogue: bias + relu
    const int crow = lane >> 2;
    const int ccol = (lane & 3) * 2;
    #pragma unroll
    for (int mb = 0; mb < 4; mb++) {
        #pragma unroll
        for (int nb = 0; nb < 4; nb++) {
            const int col = n0 + wn + nb * 8 + ccol;
            const float b0 = bias[col], b1v = bias[col + 1];
            const int row0 = m0 + wm + mb * 16 + crow;
            float2 v0, v1;
            v0.x = fmaxf(acc[mb][nb][0] + b0, 0.f);
            v0.y = fmaxf(acc[mb][nb][1] + b1v, 0.f);
            v1.x = fmaxf(acc[mb][nb][2] + b0, 0.f);
            v1.y = fmaxf(acc[mb][nb][3] + b1v, 0.f);
            *(float2*)(g_h + (size_t)row0 * HID + col)       = v0;
            *(float2*)(g_h + (size_t)(row0 + 8) * HID + col) = v1;
        }
    }
}

// ---------------------------------------------------------------------------
// GEMM2 (high accuracy): g_logits = x @ W, fp32 partials + fp64 flush (proven)
// ---------------------------------------------------------------------------
__global__ __launch_bounds__(256) void gemm_logits(
    const float* __restrict__ A, const float* __restrict__ B
) {
    const int K = DIM;
    __shared__ float As_t[32][64];
    __shared__ float Bs[32][64];

    const int tid = threadIdx.x;
    const int m0 = blockIdx.x * 64;
    const int tg4 = (tid >> 4) * 4;
    const int eg4 = (tid & 15) * 4;

    double acc[4][4];
    #pragma unroll
    for (int i = 0; i < 4; i++)
        #pragma unroll
        for (int j = 0; j < 4; j++) acc[i][j] = 0.0;

    const int ar = tid >> 3;
    const int ac = (tid & 7) * 4;

    for (int k0 = 0; k0 < K; k0 += 32) {
        __syncthreads();
        #pragma unroll
        for (int it = 0; it < 2; it++) {
            const int r = it * 32 + ar;
            float4 av = *(const float4*)(A + (size_t)(m0 + r) * K + k0 + ac);
            As_t[ac + 0][r] = av.x;
            As_t[ac + 1][r] = av.y;
            As_t[ac + 2][r] = av.z;
            As_t[ac + 3][r] = av.w;
        }
        #pragma unroll
        for (int it = 0; it < 2; it++) {
            const int f = tid * 2 + it;
            const int kk = f >> 4;
            const int e4 = (f & 15) * 4;
            *(float4*)&Bs[kk][e4] = *(const float4*)(B + (size_t)(k0 + kk) * NEXP + e4);
        }
        __syncthreads();

        float part[4][4];
        #pragma unroll
        for (int i = 0; i < 4; i++)
            #pragma unroll
            for (int j = 0; j < 4; j++) part[i][j] = 0.f;

        #pragma unroll
        for (int kk = 0; kk < 32; kk++) {
            float4 a = *(const float4*)&As_t[kk][tg4];
            float4 b = *(const float4*)&Bs[kk][eg4];
            float av[4] = {a.x, a.y, a.z, a.w};
            float bv[4] = {b.x, b.y, b.z, b.w};
            #pragma unroll
            for (int i = 0; i < 4; i++)
                #pragma unroll
                for (int j = 0; j < 4; j++)
                    part[i][j] = fmaf(av[i], bv[j], part[i][j]);
            if ((kk & 7) == 7) {
                #pragma unroll
                for (int i = 0; i < 4; i++)
                    #pragma unroll
                    for (int j = 0; j < 4; j++) {
                        acc[i][j] += (double)part[i][j];
                        part[i][j] = 0.f;
                    }
            }
        }
    }

    #pragma unroll
    for (int i = 0; i < 4; i++) {
        const int row = m0 + tg4 + i;
        #pragma unroll
        for (int j = 0; j < 4; j++)
            g_logits[(size_t)row * NEXP + eg4 + j] = (float)acc[i][j];
    }
}

// ---------------------------------------------------------------------------
// reset flag counter
// ---------------------------------------------------------------------------
__global__ void reset_flags() { g_nflag = 0; }

// ---------------------------------------------------------------------------
// predictor: z = h@W2 + b2 -> sigmoid -> dynamic_k; flag near-boundary tokens
// ---------------------------------------------------------------------------
#define ZB 1.6094379124341003f
#define ZEPS 1e-3f

__global__ __launch_bounds__(256) void predictor_k(
    const float* __restrict__ W2, const float* __restrict__ b2
) {
    __shared__ float red[256];
    const int n = blockIdx.x;
    const int tid = threadIdx.x;
    const float4* hp = (const float4*)(g_h + (size_t)n * HID);
    const float4* wp = (const float4*)W2;
    float acc = 0.f;
    #pragma unroll
    for (int j = tid; j < HID / 4; j += 256) {
        float4 h4 = hp[j];
        float4 w4 = wp[j];
        acc = fmaf(h4.x, w4.x, acc);
        acc = fmaf(h4.y, w4.y, acc);
        acc = fmaf(h4.z, w4.z, acc);
        acc = fmaf(h4.w, w4.w, acc);
    }
    red[tid] = acc;
    __syncthreads();
    for (int s = 128; s > 0; s >>= 1) {
        if (tid < s) red[tid] += red[tid + s];
        __syncthreads();
    }
    if (tid == 0) {
        float z = red[0] + b2[0];
        float score = 1.0f / (1.0f + expf(-z));
        float kf = rintf(score * 3.0f) + 1.0f;
        kf = fminf(fmaxf(kf, 1.0f), 3.0f);
        g_kdyn[n] = (int)kf;
        if (fabsf(z) < ZEPS || fabsf(z - ZB) < ZEPS || fabsf(z + ZB) < ZEPS) {
            int slot = atomicAdd(&g_nflag, 1);
            if (slot < FLAG_CAP) g_flaglist[slot] = n;
        }
    }
}

// ---------------------------------------------------------------------------
// repair: recompute z to ~fp64 accuracy for flagged tokens, overwrite g_kdyn.
// One CTA per flagged token (strided). Cost ~40us/token, ~20 tokens expected.
// ---------------------------------------------------------------------------
__global__ __launch_bounds__(256) void repair_k(
    const float* __restrict__ x, const float* __restrict__ W1,
    const float* __restrict__ b1, const float* __restrict__ W2,
    const float* __restrict__ b2
) {
    __shared__ float xs[DIM];
    __shared__ double zred[256];
    const int tid = threadIdx.x;
    const int cnt = min(g_nflag, FLAG_CAP);

    for (int w = blockIdx.x; w < cnt; w += gridDim.x) {
        const int n = g_flaglist[w];
        for (int j = tid; j < DIM / 4; j += 256)
            *(float4*)&xs[j * 4] = *(const float4*)(x + (size_t)n * DIM + j * 4);
        __syncthreads();

        double zpart = 0.0;
        #pragma unroll
        for (int t = 0; t < HID / 256; t++) {
            const int j = tid + t * 256;
            double aj = 0.0;
            for (int kc = 0; kc < DIM; kc += 64) {
                float p = 0.f;
                #pragma unroll
                for (int k = 0; k < 64; k++)
                    p = fmaf(xs[kc + k], W1[(size_t)(kc + k) * HID + j], p);
                aj += (double)p;
            }
            float hj = fmaxf((float)(aj + (double)b1[j]), 0.f);
            zpart += (double)hj * (double)W2[j];
        }
        zred[tid] = zpart;
        __syncthreads();
        for (int s = 128; s > 0; s >>= 1) {
            if (tid < s) zred[tid] += zred[tid + s];
            __syncthreads();
        }
        if (tid == 0) {
            float z = (float)(zred[0] + (double)b2[0]);
            float score = 1.0f / (1.0f + expf(-z));
            float kf = rintf(score * 3.0f) + 1.0f;
            kf = fminf(fmaxf(kf, 1.0f), 3.0f);
            g_kdyn[n] = (int)kf;
        }
        __syncthreads();
    }
}

// ---------------------------------------------------------------------------
// finalize: softmax/top-3 (rounded probs, lower-index ties)/mask/renorm
// ---------------------------------------------------------------------------
__global__ __launch_bounds__(256) void finalize(float* __restrict__ out) {
    const int warp = threadIdx.x >> 5;
    const int lane = threadIdx.x & 31;
    const int n = blockIdx.x * 8 + warp;

    const float* lp = g_logits + (size_t)n * NEXP;
    float l0 = lp[lane];
    float l1 = lp[lane + 32];

    float m = fmaxf(l0, l1);
    #pragma unroll
    for (int o = 16; o > 0; o >>= 1) m = fmaxf(m, __shfl_xor_sync(0xFFFFFFFFu, m, o));
    float e0 = expf(l0 - m);
    float e1 = expf(l1 - m);
    float s = e0 + e1;
    #pragma unroll
    for (int o = 16; o > 0; o >>= 1) s += __shfl_xor_sync(0xFFFFFFFFu, s, o);

    float p0 = e0 / s;
    float p1 = e1 / s;

    float c0 = p0, c1 = p1;
    float tv[TOPK];
    int   ti[TOPK];
    #pragma unroll
    for (int r = 0; r < TOPK; r++) {
        float v;
        int idx;
        if (c1 > c0) { v = c1; idx = lane + 32; }
        else         { v = c0; idx = lane; }
        #pragma unroll
        for (int o = 16; o > 0; o >>= 1) {
            float ov = __shfl_xor_sync(0xFFFFFFFFu, v, o);
            int   oi = __shfl_xor_sync(0xFFFFFFFFu, idx, o);
            if (ov > v || (ov == v && oi < idx)) { v = ov; idx = oi; }
        }
        tv[r] = v;
        ti[r] = idx;
        if (idx == lane)      c0 = -1.0f;
        if (idx == lane + 32) c1 = -1.0f;
    }

    const int k = g_kdyn[n];

    float msum = 0.f;
    #pragma unroll
    for (int r = 0; r < TOPK; r++)
        if (r < k) msum += tv[r];
    const float denom = msum + 1e-8f;

    if (lane < TOPK) {
        float w = (lane < k ? tv[lane] : 0.f) / denom;
        out[OFF_W + (size_t)n * TOPK + lane] = w;
        out[OFF_I + (size_t)n * TOPK + lane] = (float)ti[lane];
    }

    float m0v = 0.f, m1v = 0.f;
    #pragma unroll
    for (int r = 0; r < TOPK; r++) {
        if (r < k) {
            if (ti[r] == lane)      m0v = 1.0f;
            if (ti[r] == lane + 32) m1v = 1.0f;
        }
    }
    out[OFF_M + (size_t)n * NEXP + lane]      = m0v;
    out[OFF_M + (size_t)n * NEXP + lane + 32] = m1v;

    if (lane == 0) out[OFF_K + n] = (float)k;
}

// ---------------------------------------------------------------------------
extern "C" void kernel_launch(void* const* d_in, const int* in_sizes, int n_in,
                              void* d_out, int out_size) {
    const float* x  = (const float*)d_in[0];
    const float* W  = (const float*)d_in[1];
    const float* W1 = (const float*)d_in[2];
    const float* b1 = (const float*)d_in[3];
    const float* W2 = (const float*)d_in[4];
    const float* b2 = (const float*)d_in[5];
    float* out = (float*)d_out;

    static int smem_set = 0;
    if (!smem_set) {
        cudaFuncSetAttribute(gemm1_hmma, cudaFuncAttributeMaxDynamicSharedMemorySize, G1_SMEM);
        smem_set = 1;
    }

    split_x<<<(int)(XPLANE / (256 * 4)), 256>>>(x);
    split_w1t<<<dim3(DIM / 32, HID / 32), dim3(32, 8)>>>(W1);
    gemm1_hmma<<<dim3(HID / G1_BN, NTOK / G1_BM), 256, G1_SMEM>>>(b1);
    gemm_logits<<<NTOK / 64, 256>>>(x, W);
    reset_flags<<<1, 1>>>();
    predictor_k<<<NTOK, 256>>>(W2, b2);
    repair_k<<<64, 256>>>(x, W1, b1, W2, b2);
    finalize<<<NTOK / 8, 256>>>(out);
}